// round 11
// baseline (speedup 1.0000x reference)
#include <cuda_runtime.h>
#include <math.h>

#define NN 10000
#define EE 320000
#define EA (EE + NN)
#define HID 256

// ---------------- scratch (static device memory; no allocs allowed) ----------
__device__ float g_asum[NN];
__device__ int   g_count[NN];
__device__ float g_loop[NN];
__device__ int   g_off[NN + 1];
__device__ int   g_cursor[NN];
__device__ int   g_csr_src[EA];
__device__ float g_csr_ea[EA];
__device__ float g_xl[NN * HID];
__device__ float g_xr[NN * HID];
__device__ float g_h[NN * HID];
__device__ float g_hn[NN * HID];
__device__ float g_p1[NN * 128];
__device__ float g_logits[NN * 4];
__device__ unsigned int g_maxenc;
__device__ float g_expsum;

// ---------------- helpers ----------------------------------------------------
__device__ __forceinline__ unsigned int fenc(float f) {
    unsigned int u = __float_as_uint(f);
    return (u & 0x80000000u) ? ~u : (u | 0x80000000u);
}
__device__ __forceinline__ float fdec(unsigned int e) {
    return (e & 0x80000000u) ? __uint_as_float(e & 0x7fffffffu)
                             : __uint_as_float(~e);
}
__device__ __forceinline__ float lrelu(float v) {
    return v > 0.f ? v : 0.2f * v;
}

// ---------------- init --------------------------------------------------------
__global__ void k_init() {
    int i = blockIdx.x * blockDim.x + threadIdx.x;
    if (i < NN) { g_asum[i] = 0.f; g_count[i] = 0; g_cursor[i] = 0; }
    if (i == 0) { g_maxenc = 0u; g_expsum = 0.f; }
}

// ---------------- degree / attr sum ------------------------------------------
__global__ void k_degree(const int* __restrict__ ei, const float* __restrict__ ea) {
    int e = blockIdx.x * blockDim.x + threadIdx.x;
    if (e >= EE) return;
    int d = ei[EE + e];
    atomicAdd(&g_count[d], 1);
    atomicAdd(&g_asum[d], ea[e]);
}

// ---------------- loop attr + warp-shuffle exclusive scan of (count+1) -------
__global__ void k_scan() {
    int tid = threadIdx.x;           // 1024 threads
    // loop attr (independent of scan)
    for (int i = tid; i < NN; i += 1024)
        g_loop[i] = g_asum[i] / fmaxf((float)g_count[i], 1.f);

    const int PER = 10;              // 1024*10 >= 10000
    int base = tid * PER;
    int local[PER];
    int s = 0;
    #pragma unroll
    for (int i = 0; i < PER; ++i) {
        int idx = base + i;
        int v = (idx < NN) ? (g_count[idx] + 1) : 0;
        local[i] = s;
        s += v;
    }
    int lane = tid & 31, w = tid >> 5;
    int t = s;
    #pragma unroll
    for (int o = 1; o < 32; o <<= 1) {
        int v = __shfl_up_sync(0xffffffffu, t, o);
        if (lane >= o) t += v;
    }
    __shared__ int wsum[32];
    if (lane == 31) wsum[w] = t;
    __syncthreads();
    if (w == 0) {
        int u = wsum[lane];
        #pragma unroll
        for (int o = 1; o < 32; o <<= 1) {
            int v = __shfl_up_sync(0xffffffffu, u, o);
            if (lane >= o) u += v;
        }
        wsum[lane] = u;
    }
    __syncthreads();
    int prefix = (t - s) + (w ? wsum[w - 1] : 0);
    #pragma unroll
    for (int i = 0; i < PER; ++i) {
        int idx = base + i;
        if (idx < NN) g_off[idx] = prefix + local[i];
    }
    if (tid == 1023) g_off[NN] = wsum[31];
}

// ---------------- scatter to CSR ----------------------------------------------
__global__ void k_scatter(const int* __restrict__ ei, const float* __restrict__ ea) {
    int e = blockIdx.x * blockDim.x + threadIdx.x;
    if (e >= EA) return;
    int s, d; float a;
    if (e < EE) { s = ei[e]; d = ei[EE + e]; a = ea[e]; }
    else        { s = d = e - EE; a = g_loop[s]; }
    int pos = g_off[d] + atomicAdd(&g_cursor[d], 1);
    g_csr_src[pos] = s;
    g_csr_ea[pos]  = a;
}

// ---------------- conv1 fused edge aggregation (rank-4 trick) ------------------
// warp per dst node; lane owns 8 channels; heads = groups of 8 lanes.
// Aggregates sum_e alpha_e * x[src_e] (4 floats per head), since
// sum alpha (x@Wl + bl) = (sum alpha x)@Wl + bl.
__global__ void k_edge_agg1(const float* __restrict__ x,
                            const float* __restrict__ Wl, const float* __restrict__ bl,
                            const float* __restrict__ Wr, const float* __restrict__ br,
                            const float* __restrict__ We, const float* __restrict__ att,
                            const float* __restrict__ bias, float* __restrict__ out) {
    int warp = (blockIdx.x * blockDim.x + threadIdx.x) >> 5;
    int lane = threadIdx.x & 31;
    if (warp >= NN) return;
    int n = warp;
    int c0 = lane * 8;

    // Wl slice: wl[k][j] = Wl[k][c0+j]
    float wl[4][8];
    #pragma unroll
    for (int k = 0; k < 4; ++k) {
        float4 a = *(const float4*)(Wl + k * HID + c0);
        float4 b = *(const float4*)(Wl + k * HID + c0 + 4);
        wl[k][0] = a.x; wl[k][1] = a.y; wl[k][2] = a.z; wl[k][3] = a.w;
        wl[k][4] = b.x; wl[k][5] = b.y; wl[k][6] = b.z; wl[k][7] = b.w;
    }
    // base[j] = bl[c] + xr[n][c]  (xr = x[n]@Wr + br)
    float base[8];
    {
        float4 xn = *(const float4*)(x + n * 4);
        float xnv[4] = {xn.x, xn.y, xn.z, xn.w};
        float4 bl0 = *(const float4*)(bl + c0);
        float4 bl1 = *(const float4*)(bl + c0 + 4);
        float4 br0 = *(const float4*)(br + c0);
        float4 br1 = *(const float4*)(br + c0 + 4);
        float blv[8] = {bl0.x, bl0.y, bl0.z, bl0.w, bl1.x, bl1.y, bl1.z, bl1.w};
        float brv[8] = {br0.x, br0.y, br0.z, br0.w, br1.x, br1.y, br1.z, br1.w};
        #pragma unroll
        for (int j = 0; j < 8; ++j) {
            float s = brv[j];
            #pragma unroll
            for (int k = 0; k < 4; ++k) s += xnv[k] * Wr[k * HID + c0 + j];
            base[j] = blv[j] + s;
        }
    }
    float at[8], we[8];
    {
        float4 a0 = *(const float4*)(att + c0), a1 = *(const float4*)(att + c0 + 4);
        float4 w0 = *(const float4*)(We + c0),  w1 = *(const float4*)(We + c0 + 4);
        at[0]=a0.x; at[1]=a0.y; at[2]=a0.z; at[3]=a0.w; at[4]=a1.x; at[5]=a1.y; at[6]=a1.z; at[7]=a1.w;
        we[0]=w0.x; we[1]=w0.y; we[2]=w0.z; we[3]=w0.w; we[4]=w1.x; we[5]=w1.y; we[6]=w1.z; we[7]=w1.w;
    }

    float den = 0.f, num0 = 0.f, num1 = 0.f, num2 = 0.f, num3 = 0.f;
    int beg = g_off[n], end = g_off[n + 1];
    #pragma unroll 2
    for (int p = beg; p < end; ++p) {
        int s = g_csr_src[p];
        float ea = g_csr_ea[p];
        float4 xs = *(const float4*)(x + s * 4);
        float part = 0.f;
        #pragma unroll
        for (int j = 0; j < 8; ++j) {
            float t = base[j] + ea * we[j]
                    + xs.x * wl[0][j] + xs.y * wl[1][j]
                    + xs.z * wl[2][j] + xs.w * wl[3][j];
            part += lrelu(t) * at[j];
        }
        part += __shfl_xor_sync(0xffffffffu, part, 1);
        part += __shfl_xor_sync(0xffffffffu, part, 2);
        part += __shfl_xor_sync(0xffffffffu, part, 4);
        float w = __expf(part);       // logits bounded (|logit| < ~15): no max-shift needed
        den += w;
        num0 += w * xs.x; num1 += w * xs.y; num2 += w * xs.z; num3 += w * xs.w;
    }
    float inv = 1.f / den;
    float xb0 = num0 * inv, xb1 = num1 * inv, xb2 = num2 * inv, xb3 = num3 * inv;

    float4 bl0 = *(const float4*)(bl + c0), bl1 = *(const float4*)(bl + c0 + 4);
    float4 bi0 = *(const float4*)(bias + c0), bi1 = *(const float4*)(bias + c0 + 4);
    float blv[8] = {bl0.x, bl0.y, bl0.z, bl0.w, bl1.x, bl1.y, bl1.z, bl1.w};
    float biv[8] = {bi0.x, bi0.y, bi0.z, bi0.w, bi1.x, bi1.y, bi1.z, bi1.w};
    float o[8];
    #pragma unroll
    for (int j = 0; j < 8; ++j)
        o[j] = xb0 * wl[0][j] + xb1 * wl[1][j] + xb2 * wl[2][j] + xb3 * wl[3][j]
             + blv[j] + biv[j];
    float4* op = (float4*)(out + (size_t)n * HID + c0);
    op[0] = make_float4(o[0], o[1], o[2], o[3]);
    op[1] = make_float4(o[4], o[5], o[6], o[7]);
}

// ---------------- conv2 edge aggregation (H=1, gather xl2) --------------------
__global__ void k_edge_agg2(const float* __restrict__ We, const float* __restrict__ att,
                            const float* __restrict__ bias, float* __restrict__ out) {
    int warp = (blockIdx.x * blockDim.x + threadIdx.x) >> 5;
    int lane = threadIdx.x & 31;
    if (warp >= NN) return;
    int n = warp;
    int c0 = lane * 8;

    float4 at0 = *(const float4*)(att + c0);
    float4 at1 = *(const float4*)(att + c0 + 4);
    float4 we0 = *(const float4*)(We + c0);
    float4 we1 = *(const float4*)(We + c0 + 4);
    const float4* xrp = (const float4*)(g_xr + (size_t)n * HID + c0);
    float4 xr0 = xrp[0], xr1 = xrp[1];

    float num[8];
    #pragma unroll
    for (int i = 0; i < 8; ++i) num[i] = 0.f;
    float den = 0.f;

    int beg = g_off[n], end = g_off[n + 1];
    #pragma unroll 2
    for (int p = beg; p < end; ++p) {
        int s = g_csr_src[p];
        float ea = g_csr_ea[p];
        const float4* xsp = (const float4*)(g_xl + (size_t)s * HID + c0);
        float4 a = xsp[0], b = xsp[1];
        float part;
        part  = lrelu(a.x + xr0.x + ea * we0.x) * at0.x;
        part += lrelu(a.y + xr0.y + ea * we0.y) * at0.y;
        part += lrelu(a.z + xr0.z + ea * we0.z) * at0.z;
        part += lrelu(a.w + xr0.w + ea * we0.w) * at0.w;
        part += lrelu(b.x + xr1.x + ea * we1.x) * at1.x;
        part += lrelu(b.y + xr1.y + ea * we1.y) * at1.y;
        part += lrelu(b.z + xr1.z + ea * we1.z) * at1.z;
        part += lrelu(b.w + xr1.w + ea * we1.w) * at1.w;
        #pragma unroll
        for (int o = 1; o < 32; o <<= 1)
            part += __shfl_xor_sync(0xffffffffu, part, o);
        float w = __expf(part);
        den += w;
        num[0] += w * a.x; num[1] += w * a.y; num[2] += w * a.z; num[3] += w * a.w;
        num[4] += w * b.x; num[5] += w * b.y; num[6] += w * b.z; num[7] += w * b.w;
    }
    float inv = 1.f / den;
    float4 bi0 = *(const float4*)(bias + c0);
    float4 bi1 = *(const float4*)(bias + c0 + 4);
    float4* op = (float4*)(out + (size_t)n * HID + c0);
    op[0] = make_float4(num[0]*inv + bi0.x, num[1]*inv + bi0.y,
                        num[2]*inv + bi0.z, num[3]*inv + bi0.w);
    op[1] = make_float4(num[4]*inv + bi1.x, num[5]*inv + bi1.y,
                        num[6]*inv + bi1.z, num[7]*inv + bi1.w);
}

// ---------------- layernorm + relu (warp per node) ----------------------------
__global__ void k_ln_relu(const float* __restrict__ in, const float* __restrict__ g,
                          const float* __restrict__ b, float* __restrict__ out) {
    int warp = (blockIdx.x * blockDim.x + threadIdx.x) >> 5;
    int lane = threadIdx.x & 31;
    if (warp >= NN) return;
    int n = warp;
    int c0 = lane * 8;
    const float4* ip = (const float4*)(in + (size_t)n * HID + c0);
    float4 v0 = ip[0], v1 = ip[1];
    float s = v0.x + v0.y + v0.z + v0.w + v1.x + v1.y + v1.z + v1.w;
    #pragma unroll
    for (int o = 16; o > 0; o >>= 1) s += __shfl_xor_sync(0xffffffffu, s, o);
    float mu = s * (1.f / HID);
    float d0x = v0.x - mu, d0y = v0.y - mu, d0z = v0.z - mu, d0w = v0.w - mu;
    float d1x = v1.x - mu, d1y = v1.y - mu, d1z = v1.z - mu, d1w = v1.w - mu;
    float ss = d0x*d0x + d0y*d0y + d0z*d0z + d0w*d0w
             + d1x*d1x + d1y*d1y + d1z*d1z + d1w*d1w;
    #pragma unroll
    for (int o = 16; o > 0; o >>= 1) ss += __shfl_xor_sync(0xffffffffu, ss, o);
    float rstd = rsqrtf(ss * (1.f / HID) + 1e-5f);
    float4 gg0 = *(const float4*)(g + c0), gg1 = *(const float4*)(g + c0 + 4);
    float4 bb0 = *(const float4*)(b + c0), bb1 = *(const float4*)(b + c0 + 4);
    float4 o0, o1;
    o0.x = fmaxf(0.f, d0x * rstd * gg0.x + bb0.x);
    o0.y = fmaxf(0.f, d0y * rstd * gg0.y + bb0.y);
    o0.z = fmaxf(0.f, d0z * rstd * gg0.z + bb0.z);
    o0.w = fmaxf(0.f, d0w * rstd * gg0.w + bb0.w);
    o1.x = fmaxf(0.f, d1x * rstd * gg1.x + bb1.x);
    o1.y = fmaxf(0.f, d1y * rstd * gg1.y + bb1.y);
    o1.z = fmaxf(0.f, d1z * rstd * gg1.z + bb1.z);
    o1.w = fmaxf(0.f, d1w * rstd * gg1.w + bb1.w);
    float4* op = (float4*)(out + (size_t)n * HID + c0);
    op[0] = o0; op[1] = o1;
}

// ---------------- dual SGEMM: [C0|C1] = A @ [B0|B1] + bias, 128x128 tiles -----
// A: M x 256, B0/B1: 256 x 256 row-major, C0/C1: M x 256. grid (4, ceil(M/128)).
__global__ void k_gemm_dual(const float* __restrict__ A,
                            const float* __restrict__ B0, const float* __restrict__ B1,
                            const float* __restrict__ bias0, const float* __restrict__ bias1,
                            float* __restrict__ C0, float* __restrict__ C1, int M) {
    const int K = 256;
    __shared__ float As[16][132];
    __shared__ float Bs[16][128];
    int col0 = blockIdx.x * 128;
    const float* B; const float* bias; float* C; int cc;
    if (col0 < 256) { B = B0; bias = bias0; C = C0; cc = col0; }
    else            { B = B1; bias = bias1; C = C1; cc = col0 - 256; }
    int row0 = blockIdx.y * 128;
    int tid = threadIdx.x;
    int tx = tid & 15, ty = tid >> 4;

    float acc[8][8];
    #pragma unroll
    for (int i = 0; i < 8; ++i)
        #pragma unroll
        for (int j = 0; j < 8; ++j) acc[i][j] = 0.f;

    float4 pa[2], pb[2];
    // prologue: load k-block 0
    #pragma unroll
    for (int u = 0; u < 2; ++u) {
        int f = tid + u * 256;
        int r = f >> 2, kc = (f & 3) << 2;
        int grow = row0 + r;
        pa[u] = (grow < M) ? *(const float4*)(A + (size_t)grow * K + kc)
                           : make_float4(0.f, 0.f, 0.f, 0.f);
        int rb = f >> 5, cb = (f & 31) << 2;
        pb[u] = *(const float4*)(B + (size_t)rb * 256 + cc + cb);
    }

    for (int kb = 0; kb < K / 16; ++kb) {
        // store prefetched tile to smem
        #pragma unroll
        for (int u = 0; u < 2; ++u) {
            int f = tid + u * 256;
            int r = f >> 2, kc = (f & 3) << 2;
            As[kc + 0][r] = pa[u].x; As[kc + 1][r] = pa[u].y;
            As[kc + 2][r] = pa[u].z; As[kc + 3][r] = pa[u].w;
            int rb = f >> 5, cb = (f & 31) << 2;
            *(float4*)&Bs[rb][cb] = pb[u];
        }
        __syncthreads();
        // prefetch next k-block
        if (kb + 1 < K / 16) {
            int k0 = (kb + 1) * 16;
            #pragma unroll
            for (int u = 0; u < 2; ++u) {
                int f = tid + u * 256;
                int r = f >> 2, kc = (f & 3) << 2;
                int grow = row0 + r;
                pa[u] = (grow < M) ? *(const float4*)(A + (size_t)grow * K + k0 + kc)
                                   : make_float4(0.f, 0.f, 0.f, 0.f);
                int rb = f >> 5, cb = (f & 31) << 2;
                pb[u] = *(const float4*)(B + (size_t)(k0 + rb) * 256 + cc + cb);
            }
        }
        // compute
        #pragma unroll
        for (int kk = 0; kk < 16; ++kk) {
            float4 a0 = *(float4*)&As[kk][ty * 8];
            float4 a1 = *(float4*)&As[kk][ty * 8 + 4];
            float4 b0 = *(float4*)&Bs[kk][tx * 8];
            float4 b1 = *(float4*)&Bs[kk][tx * 8 + 4];
            float av[8] = {a0.x, a0.y, a0.z, a0.w, a1.x, a1.y, a1.z, a1.w};
            float bv[8] = {b0.x, b0.y, b0.z, b0.w, b1.x, b1.y, b1.z, b1.w};
            #pragma unroll
            for (int i = 0; i < 8; ++i)
                #pragma unroll
                for (int j = 0; j < 8; ++j) acc[i][j] += av[i] * bv[j];
        }
        __syncthreads();
    }

    float4 bv0 = *(const float4*)(bias + cc + tx * 8);
    float4 bv1 = *(const float4*)(bias + cc + tx * 8 + 4);
    #pragma unroll
    for (int i = 0; i < 8; ++i) {
        int grow = row0 + ty * 8 + i;
        if (grow >= M) continue;
        float4 o0 = make_float4(acc[i][0] + bv0.x, acc[i][1] + bv0.y,
                                acc[i][2] + bv0.z, acc[i][3] + bv0.w);
        float4 o1 = make_float4(acc[i][4] + bv1.x, acc[i][5] + bv1.y,
                                acc[i][6] + bv1.z, acc[i][7] + bv1.w);
        float4* cp = (float4*)(C + (size_t)grow * 256 + cc + tx * 8);
        cp[0] = o0; cp[1] = o1;
    }
}

// ---------------- policy SGEMM: C = relu(A @ B + bias), 64x128 tiles ----------
// A: M x 256, B: 256 x 128, C: M x 128. grid (1, ceil(M/64)).
__global__ void k_gemm_p(const float* __restrict__ A, const float* __restrict__ B,
                         const float* __restrict__ bias, float* __restrict__ C, int M) {
    const int K = 256;
    __shared__ float As[16][68];
    __shared__ float Bs[16][128];
    int row0 = blockIdx.y * 64;
    int tid = threadIdx.x;
    int tx = tid & 15, ty = tid >> 4;

    float acc[4][8];
    #pragma unroll
    for (int i = 0; i < 4; ++i)
        #pragma unroll
        for (int j = 0; j < 8; ++j) acc[i][j] = 0.f;

    float4 pa, pb[2];
    {
        int r = tid >> 2, kc = (tid & 3) << 2;
        int grow = row0 + r;
        pa = (grow < M) ? *(const float4*)(A + (size_t)grow * K + kc)
                        : make_float4(0.f, 0.f, 0.f, 0.f);
        #pragma unroll
        for (int u = 0; u < 2; ++u) {
            int f = tid + u * 256;
            int rb = f >> 5, cb = (f & 31) << 2;
            pb[u] = *(const float4*)(B + (size_t)rb * 128 + cb);
        }
    }

    for (int kb = 0; kb < K / 16; ++kb) {
        {
            int r = tid >> 2, kc = (tid & 3) << 2;
            As[kc + 0][r] = pa.x; As[kc + 1][r] = pa.y;
            As[kc + 2][r] = pa.z; As[kc + 3][r] = pa.w;
            #pragma unroll
            for (int u = 0; u < 2; ++u) {
                int f = tid + u * 256;
                int rb = f >> 5, cb = (f & 31) << 2;
                *(float4*)&Bs[rb][cb] = pb[u];
            }
        }
        __syncthreads();
        if (kb + 1 < K / 16) {
            int k0 = (kb + 1) * 16;
            int r = tid >> 2, kc = (tid & 3) << 2;
            int grow = row0 + r;
            pa = (grow < M) ? *(const float4*)(A + (size_t)grow * K + k0 + kc)
                            : make_float4(0.f, 0.f, 0.f, 0.f);
            #pragma unroll
            for (int u = 0; u < 2; ++u) {
                int f = tid + u * 256;
                int rb = f >> 5, cb = (f & 31) << 2;
                pb[u] = *(const float4*)(B + (size_t)(k0 + rb) * 128 + cb);
            }
        }
        #pragma unroll
        for (int kk = 0; kk < 16; ++kk) {
            float4 a0 = *(float4*)&As[kk][ty * 4];
            float4 b0 = *(float4*)&Bs[kk][tx * 8];
            float4 b1 = *(float4*)&Bs[kk][tx * 8 + 4];
            float av[4] = {a0.x, a0.y, a0.z, a0.w};
            float bv[8] = {b0.x, b0.y, b0.z, b0.w, b1.x, b1.y, b1.z, b1.w};
            #pragma unroll
            for (int i = 0; i < 4; ++i)
                #pragma unroll
                for (int j = 0; j < 8; ++j) acc[i][j] += av[i] * bv[j];
        }
        __syncthreads();
    }

    float4 bv0 = *(const float4*)(bias + tx * 8);
    float4 bv1 = *(const float4*)(bias + tx * 8 + 4);
    #pragma unroll
    for (int i = 0; i < 4; ++i) {
        int grow = row0 + ty * 4 + i;
        if (grow >= M) continue;
        float4 o0 = make_float4(fmaxf(acc[i][0] + bv0.x, 0.f), fmaxf(acc[i][1] + bv0.y, 0.f),
                                fmaxf(acc[i][2] + bv0.z, 0.f), fmaxf(acc[i][3] + bv0.w, 0.f));
        float4 o1 = make_float4(fmaxf(acc[i][4] + bv1.x, 0.f), fmaxf(acc[i][5] + bv1.y, 0.f),
                                fmaxf(acc[i][6] + bv1.z, 0.f), fmaxf(acc[i][7] + bv1.w, 0.f));
        float4* cp = (float4*)(C + (size_t)grow * 128 + tx * 8);
        cp[0] = o0; cp[1] = o1;
    }
}

// ---------------- p1 @ Wp2 + bp2 -> logits (warp per node) --------------------
__global__ void k_wp2(const float* __restrict__ Wp2, const float* __restrict__ bp2) {
    __shared__ float Ws[128 * 4];
    int tid = threadIdx.x;
    for (int i = tid; i < 128 * 4; i += blockDim.x) Ws[i] = Wp2[i];
    __syncthreads();
    int warp = (blockIdx.x * blockDim.x + tid) >> 5;
    int lane = tid & 31;
    if (warp >= NN) return;
    int n = warp;
    float o[4] = {0.f, 0.f, 0.f, 0.f};
    #pragma unroll
    for (int i = 0; i < 4; ++i) {
        int k = lane + 32 * i;
        float p = g_p1[(size_t)n * 128 + k];
        #pragma unroll
        for (int j = 0; j < 4; ++j) o[j] += p * Ws[k * 4 + j];
    }
    #pragma unroll
    for (int j = 0; j < 4; ++j) {
        #pragma unroll
        for (int off = 16; off > 0; off >>= 1)
            o[j] += __shfl_xor_sync(0xffffffffu, o[j], off);
    }
    if (lane == 0) {
        #pragma unroll
        for (int j = 0; j < 4; ++j) g_logits[n * 4 + j] = o[j] + bp2[j];
    }
}

// ---------------- global softmax over 40000 logits ----------------------------
__global__ void k_max() {
    __shared__ float sm[256];
    float m = -1e30f;
    for (int i = blockIdx.x * blockDim.x + threadIdx.x; i < NN * 4;
         i += gridDim.x * blockDim.x)
        m = fmaxf(m, g_logits[i]);
    sm[threadIdx.x] = m;
    __syncthreads();
    for (int o = 128; o > 0; o >>= 1) {
        if (threadIdx.x < o) sm[threadIdx.x] = fmaxf(sm[threadIdx.x], sm[threadIdx.x + o]);
        __syncthreads();
    }
    if (threadIdx.x == 0) atomicMax(&g_maxenc, fenc(sm[0]));
}

__global__ void k_expsum() {
    __shared__ float sm[256];
    float M = fdec(g_maxenc);
    float s = 0.f;
    for (int i = blockIdx.x * blockDim.x + threadIdx.x; i < NN * 4;
         i += gridDim.x * blockDim.x)
        s += expf(g_logits[i] - M);
    sm[threadIdx.x] = s;
    __syncthreads();
    for (int o = 128; o > 0; o >>= 1) {
        if (threadIdx.x < o) sm[threadIdx.x] += sm[threadIdx.x + o];
        __syncthreads();
    }
    if (threadIdx.x == 0) atomicAdd(&g_expsum, sm[0]);
}

__global__ void k_out(float* __restrict__ out) {
    int i = blockIdx.x * blockDim.x + threadIdx.x;
    if (i >= NN * 4) return;
    float M = fdec(g_maxenc);
    float inv = 1.f / g_expsum;
    out[i] = expf(g_logits[i] - M) * inv;
}

// ---------------- launch ------------------------------------------------------
// NOTE: __device__ symbols must NOT be passed directly as kernel args from host
// code (ATS silently reads the host shadow). Use cudaGetSymbolAddress.
extern "C" void kernel_launch(void* const* d_in, const int* in_sizes, int n_in,
                              void* d_out, int out_size) {
    const float* x     = (const float*)d_in[0];
    const int*   ei    = (const int*)d_in[1];
    const float* eattr = (const float*)d_in[2];
    const float* Wl1 = (const float*)d_in[3];
    const float* bl1 = (const float*)d_in[4];
    const float* Wr1 = (const float*)d_in[5];
    const float* br1 = (const float*)d_in[6];
    const float* We1 = (const float*)d_in[7];
    const float* att1 = (const float*)d_in[8];
    const float* bias1 = (const float*)d_in[9];
    const float* g1  = (const float*)d_in[10];
    const float* be1 = (const float*)d_in[11];
    const float* Wl2 = (const float*)d_in[12];
    const float* bl2 = (const float*)d_in[13];
    const float* Wr2 = (const float*)d_in[14];
    const float* br2 = (const float*)d_in[15];
    const float* We2 = (const float*)d_in[16];
    const float* att2 = (const float*)d_in[17];
    const float* bias2 = (const float*)d_in[18];
    const float* g2  = (const float*)d_in[19];
    const float* be2 = (const float*)d_in[20];
    const float* Wp1 = (const float*)d_in[21];
    const float* bp1 = (const float*)d_in[22];
    const float* Wp2 = (const float*)d_in[23];
    const float* bp2 = (const float*)d_in[24];
    float* out = (float*)d_out;

    void* pv;
    float *xl, *xr, *h, *hn, *p1;
    cudaGetSymbolAddress(&pv, g_xl);  xl = (float*)pv;
    cudaGetSymbolAddress(&pv, g_xr);  xr = (float*)pv;
    cudaGetSymbolAddress(&pv, g_h);   h  = (float*)pv;
    cudaGetSymbolAddress(&pv, g_hn);  hn = (float*)pv;
    cudaGetSymbolAddress(&pv, g_p1);  p1 = (float*)pv;

    // preprocessing
    k_init<<<(NN + 255) / 256, 256>>>();
    k_degree<<<(EE + 255) / 256, 256>>>(ei, eattr);
    k_scan<<<1, 1024>>>();
    k_scatter<<<(EA + 255) / 256, 256>>>(ei, eattr);

    // conv1 (H=4, C=64): fused rank-4 aggregation
    k_edge_agg1<<<(NN * 32 + 255) / 256, 256>>>(x, Wl1, bl1, Wr1, br1, We1, att1, bias1, h);
    k_ln_relu<<<(NN * 32 + 255) / 256, 256>>>(h, g1, be1, hn);

    // conv2 (H=1, C=256): fused dual GEMM then gather-aggregate
    dim3 gD(4, (NN + 127) / 128);
    k_gemm_dual<<<gD, 256>>>(hn, Wl2, Wr2, bl2, br2, xl, xr, NN);
    k_edge_agg2<<<(NN * 32 + 255) / 256, 256>>>(We2, att2, bias2, h);
    k_ln_relu<<<(NN * 32 + 255) / 256, 256>>>(h, g2, be2, hn);

    // policy head
    dim3 gP(1, (NN + 63) / 64);
    k_gemm_p<<<gP, 256>>>(hn, Wp1, bp1, p1, NN);
    k_wp2<<<(NN * 32 + 255) / 256, 256>>>(Wp2, bp2);

    // global softmax
    k_max<<<64, 256>>>();
    k_expsum<<<64, 256>>>();
    k_out<<<(NN * 4 + 255) / 256, 256>>>(out);
}

// round 14
// speedup vs baseline: 1.0022x; 1.0022x over previous
#include <cuda_runtime.h>
#include <math.h>

#define NN 10000
#define EE 320000
#define EA (EE + NN)
#define HID 256

// ---------------- scratch (static device memory; no allocs allowed) ----------
__device__ float g_asum[NN];
__device__ int   g_count[NN];
__device__ float g_loop[NN];
__device__ int   g_off[NN + 1];
__device__ int   g_cursor[NN];
__device__ int   g_csr_src[EA];
__device__ float g_csr_ea[EA];
__device__ float g_xl[NN * HID];
__device__ float g_xr[NN * HID];
__device__ float g_h[NN * HID];
__device__ float g_hn[NN * HID];
__device__ float g_p1[NN * 128];
__device__ float g_logits[NN * 4];

// ---------------- helpers ----------------------------------------------------
__device__ __forceinline__ float lrelu(float v) {
    return v > 0.f ? v : 0.2f * v;
}

// ---------------- init --------------------------------------------------------
__global__ void k_init() {
    int i = blockIdx.x * blockDim.x + threadIdx.x;
    if (i < NN) { g_asum[i] = 0.f; g_count[i] = 0; g_cursor[i] = 0; }
}

// ---------------- degree / attr sum ------------------------------------------
__global__ void k_degree(const int* __restrict__ ei, const float* __restrict__ ea) {
    int e = blockIdx.x * blockDim.x + threadIdx.x;
    if (e >= EE) return;
    int d = ei[EE + e];
    atomicAdd(&g_count[d], 1);
    atomicAdd(&g_asum[d], ea[e]);
}

// ---------------- loop attr + warp-shuffle exclusive scan of (count+1) -------
__global__ void k_scan() {
    int tid = threadIdx.x;           // 1024 threads
    for (int i = tid; i < NN; i += 1024)
        g_loop[i] = g_asum[i] / fmaxf((float)g_count[i], 1.f);

    const int PER = 10;
    int base = tid * PER;
    int local[PER];
    int s = 0;
    #pragma unroll
    for (int i = 0; i < PER; ++i) {
        int idx = base + i;
        int v = (idx < NN) ? (g_count[idx] + 1) : 0;
        local[i] = s;
        s += v;
    }
    int lane = tid & 31, w = tid >> 5;
    int t = s;
    #pragma unroll
    for (int o = 1; o < 32; o <<= 1) {
        int v = __shfl_up_sync(0xffffffffu, t, o);
        if (lane >= o) t += v;
    }
    __shared__ int wsum[32];
    if (lane == 31) wsum[w] = t;
    __syncthreads();
    if (w == 0) {
        int u = wsum[lane];
        #pragma unroll
        for (int o = 1; o < 32; o <<= 1) {
            int v = __shfl_up_sync(0xffffffffu, u, o);
            if (lane >= o) u += v;
        }
        wsum[lane] = u;
    }
    __syncthreads();
    int prefix = (t - s) + (w ? wsum[w - 1] : 0);
    #pragma unroll
    for (int i = 0; i < PER; ++i) {
        int idx = base + i;
        if (idx < NN) g_off[idx] = prefix + local[i];
    }
    if (tid == 1023) g_off[NN] = wsum[31];
}

// ---------------- scatter to CSR ----------------------------------------------
__global__ void k_scatter(const int* __restrict__ ei, const float* __restrict__ ea) {
    int e = blockIdx.x * blockDim.x + threadIdx.x;
    if (e >= EA) return;
    int s, d; float a;
    if (e < EE) { s = ei[e]; d = ei[EE + e]; a = ea[e]; }
    else        { s = d = e - EE; a = g_loop[s]; }
    int pos = g_off[d] + atomicAdd(&g_cursor[d], 1);
    g_csr_src[pos] = s;
    g_csr_ea[pos]  = a;
}

// ---------------- conv1 fused edge aggregation (rank-4 trick) ------------------
__global__ void k_edge_agg1(const float* __restrict__ x,
                            const float* __restrict__ Wl, const float* __restrict__ bl,
                            const float* __restrict__ Wr, const float* __restrict__ br,
                            const float* __restrict__ We, const float* __restrict__ att,
                            const float* __restrict__ bias, float* __restrict__ out) {
    int warp = (blockIdx.x * blockDim.x + threadIdx.x) >> 5;
    int lane = threadIdx.x & 31;
    if (warp >= NN) return;
    int n = warp;
    int c0 = lane * 8;

    float wl[4][8];
    #pragma unroll
    for (int k = 0; k < 4; ++k) {
        float4 a = *(const float4*)(Wl + k * HID + c0);
        float4 b = *(const float4*)(Wl + k * HID + c0 + 4);
        wl[k][0] = a.x; wl[k][1] = a.y; wl[k][2] = a.z; wl[k][3] = a.w;
        wl[k][4] = b.x; wl[k][5] = b.y; wl[k][6] = b.z; wl[k][7] = b.w;
    }
    float base[8];
    {
        float4 xn = *(const float4*)(x + n * 4);
        float xnv[4] = {xn.x, xn.y, xn.z, xn.w};
        float4 bl0 = *(const float4*)(bl + c0);
        float4 bl1 = *(const float4*)(bl + c0 + 4);
        float4 br0 = *(const float4*)(br + c0);
        float4 br1 = *(const float4*)(br + c0 + 4);
        float blv[8] = {bl0.x, bl0.y, bl0.z, bl0.w, bl1.x, bl1.y, bl1.z, bl1.w};
        float brv[8] = {br0.x, br0.y, br0.z, br0.w, br1.x, br1.y, br1.z, br1.w};
        #pragma unroll
        for (int j = 0; j < 8; ++j) {
            float s = brv[j];
            #pragma unroll
            for (int k = 0; k < 4; ++k) s += xnv[k] * Wr[k * HID + c0 + j];
            base[j] = blv[j] + s;
        }
    }
    float at[8], we[8];
    {
        float4 a0 = *(const float4*)(att + c0), a1 = *(const float4*)(att + c0 + 4);
        float4 w0 = *(const float4*)(We + c0),  w1 = *(const float4*)(We + c0 + 4);
        at[0]=a0.x; at[1]=a0.y; at[2]=a0.z; at[3]=a0.w; at[4]=a1.x; at[5]=a1.y; at[6]=a1.z; at[7]=a1.w;
        we[0]=w0.x; we[1]=w0.y; we[2]=w0.z; we[3]=w0.w; we[4]=w1.x; we[5]=w1.y; we[6]=w1.z; we[7]=w1.w;
    }

    float den = 0.f, num0 = 0.f, num1 = 0.f, num2 = 0.f, num3 = 0.f;
    int beg = g_off[n], end = g_off[n + 1];
    #pragma unroll 2
    for (int p = beg; p < end; ++p) {
        int s = g_csr_src[p];
        float ea = g_csr_ea[p];
        float4 xs = *(const float4*)(x + s * 4);
        float part = 0.f;
        #pragma unroll
        for (int j = 0; j < 8; ++j) {
            float t = base[j] + ea * we[j]
                    + xs.x * wl[0][j] + xs.y * wl[1][j]
                    + xs.z * wl[2][j] + xs.w * wl[3][j];
            part += lrelu(t) * at[j];
        }
        part += __shfl_xor_sync(0xffffffffu, part, 1);
        part += __shfl_xor_sync(0xffffffffu, part, 2);
        part += __shfl_xor_sync(0xffffffffu, part, 4);
        float w = __expf(part);
        den += w;
        num0 += w * xs.x; num1 += w * xs.y; num2 += w * xs.z; num3 += w * xs.w;
    }
    float inv = 1.f / den;
    float xb0 = num0 * inv, xb1 = num1 * inv, xb2 = num2 * inv, xb3 = num3 * inv;

    float4 bl0 = *(const float4*)(bl + c0), bl1 = *(const float4*)(bl + c0 + 4);
    float4 bi0 = *(const float4*)(bias + c0), bi1 = *(const float4*)(bias + c0 + 4);
    float blv[8] = {bl0.x, bl0.y, bl0.z, bl0.w, bl1.x, bl1.y, bl1.z, bl1.w};
    float biv[8] = {bi0.x, bi0.y, bi0.z, bi0.w, bi1.x, bi1.y, bi1.z, bi1.w};
    float o[8];
    #pragma unroll
    for (int j = 0; j < 8; ++j)
        o[j] = xb0 * wl[0][j] + xb1 * wl[1][j] + xb2 * wl[2][j] + xb3 * wl[3][j]
             + blv[j] + biv[j];
    float4* op = (float4*)(out + (size_t)n * HID + c0);
    op[0] = make_float4(o[0], o[1], o[2], o[3]);
    op[1] = make_float4(o[4], o[5], o[6], o[7]);
}

// ---------------- conv2 edge aggregation (H=1, gather xl2) --------------------
__global__ void k_edge_agg2(const float* __restrict__ We, const float* __restrict__ att,
                            const float* __restrict__ bias, float* __restrict__ out) {
    int warp = (blockIdx.x * blockDim.x + threadIdx.x) >> 5;
    int lane = threadIdx.x & 31;
    if (warp >= NN) return;
    int n = warp;
    int c0 = lane * 8;

    float4 at0 = *(const float4*)(att + c0);
    float4 at1 = *(const float4*)(att + c0 + 4);
    float4 we0 = *(const float4*)(We + c0);
    float4 we1 = *(const float4*)(We + c0 + 4);
    const float4* xrp = (const float4*)(g_xr + (size_t)n * HID + c0);
    float4 xr0 = xrp[0], xr1 = xrp[1];

    float num[8];
    #pragma unroll
    for (int i = 0; i < 8; ++i) num[i] = 0.f;
    float den = 0.f;

    int beg = g_off[n], end = g_off[n + 1];
    #pragma unroll 2
    for (int p = beg; p < end; ++p) {
        int s = g_csr_src[p];
        float ea = g_csr_ea[p];
        const float4* xsp = (const float4*)(g_xl + (size_t)s * HID + c0);
        float4 a = xsp[0], b = xsp[1];
        float part;
        part  = lrelu(a.x + xr0.x + ea * we0.x) * at0.x;
        part += lrelu(a.y + xr0.y + ea * we0.y) * at0.y;
        part += lrelu(a.z + xr0.z + ea * we0.z) * at0.z;
        part += lrelu(a.w + xr0.w + ea * we0.w) * at0.w;
        part += lrelu(b.x + xr1.x + ea * we1.x) * at1.x;
        part += lrelu(b.y + xr1.y + ea * we1.y) * at1.y;
        part += lrelu(b.z + xr1.z + ea * we1.z) * at1.z;
        part += lrelu(b.w + xr1.w + ea * we1.w) * at1.w;
        #pragma unroll
        for (int o = 1; o < 32; o <<= 1)
            part += __shfl_xor_sync(0xffffffffu, part, o);
        float w = __expf(part);
        den += w;
        num[0] += w * a.x; num[1] += w * a.y; num[2] += w * a.z; num[3] += w * a.w;
        num[4] += w * b.x; num[5] += w * b.y; num[6] += w * b.z; num[7] += w * b.w;
    }
    float inv = 1.f / den;
    float4 bi0 = *(const float4*)(bias + c0);
    float4 bi1 = *(const float4*)(bias + c0 + 4);
    float4* op = (float4*)(out + (size_t)n * HID + c0);
    op[0] = make_float4(num[0]*inv + bi0.x, num[1]*inv + bi0.y,
                        num[2]*inv + bi0.z, num[3]*inv + bi0.w);
    op[1] = make_float4(num[4]*inv + bi1.x, num[5]*inv + bi1.y,
                        num[6]*inv + bi1.z, num[7]*inv + bi1.w);
}

// ---------------- layernorm + relu (warp per node) ----------------------------
__global__ void k_ln_relu(const float* __restrict__ in, const float* __restrict__ g,
                          const float* __restrict__ b, float* __restrict__ out) {
    int warp = (blockIdx.x * blockDim.x + threadIdx.x) >> 5;
    int lane = threadIdx.x & 31;
    if (warp >= NN) return;
    int n = warp;
    int c0 = lane * 8;
    const float4* ip = (const float4*)(in + (size_t)n * HID + c0);
    float4 v0 = ip[0], v1 = ip[1];
    float s = v0.x + v0.y + v0.z + v0.w + v1.x + v1.y + v1.z + v1.w;
    #pragma unroll
    for (int o = 16; o > 0; o >>= 1) s += __shfl_xor_sync(0xffffffffu, s, o);
    float mu = s * (1.f / HID);
    float d0x = v0.x - mu, d0y = v0.y - mu, d0z = v0.z - mu, d0w = v0.w - mu;
    float d1x = v1.x - mu, d1y = v1.y - mu, d1z = v1.z - mu, d1w = v1.w - mu;
    float ss = d0x*d0x + d0y*d0y + d0z*d0z + d0w*d0w
             + d1x*d1x + d1y*d1y + d1z*d1z + d1w*d1w;
    #pragma unroll
    for (int o = 16; o > 0; o >>= 1) ss += __shfl_xor_sync(0xffffffffu, ss, o);
    float rstd = rsqrtf(ss * (1.f / HID) + 1e-5f);
    float4 gg0 = *(const float4*)(g + c0), gg1 = *(const float4*)(g + c0 + 4);
    float4 bb0 = *(const float4*)(b + c0), bb1 = *(const float4*)(b + c0 + 4);
    float4 o0, o1;
    o0.x = fmaxf(0.f, d0x * rstd * gg0.x + bb0.x);
    o0.y = fmaxf(0.f, d0y * rstd * gg0.y + bb0.y);
    o0.z = fmaxf(0.f, d0z * rstd * gg0.z + bb0.z);
    o0.w = fmaxf(0.f, d0w * rstd * gg0.w + bb0.w);
    o1.x = fmaxf(0.f, d1x * rstd * gg1.x + bb1.x);
    o1.y = fmaxf(0.f, d1y * rstd * gg1.y + bb1.y);
    o1.z = fmaxf(0.f, d1z * rstd * gg1.z + bb1.z);
    o1.w = fmaxf(0.f, d1w * rstd * gg1.w + bb1.w);
    float4* op = (float4*)(out + (size_t)n * HID + c0);
    op[0] = o0; op[1] = o1;
}

// ---------------- SGEMM 64x128 tile, 128 threads, 8x8 micro -------------------
// Wave-model: ~120 regs -> 4 CTAs/SM; LDS = 1 B/FMA (at the 128 B/cyc limit).
// Dual variant: flat grid 157*4; q = bx&3: mat = q>>1, colhalf = q&1.
__global__ void __launch_bounds__(128, 4)
k_gemm_dual(const float* __restrict__ A,
            const float* __restrict__ B0, const float* __restrict__ B1,
            const float* __restrict__ bias0, const float* __restrict__ bias1,
            float* __restrict__ C0, float* __restrict__ C1, int M) {
    const int K = 256;
    __shared__ float As[16][68];
    __shared__ float Bs[16][128];
    int bx = blockIdx.x;
    int mt = bx >> 2, q = bx & 3;
    const float* B; const float* bias; float* C;
    if (q < 2) { B = B0; bias = bias0; C = C0; }
    else       { B = B1; bias = bias1; C = C1; }
    int cc = (q & 1) * 128;
    int row0 = mt * 64;
    int tid = threadIdx.x;
    int tx = tid & 15, ty = tid >> 4;

    float acc[8][8];
    #pragma unroll
    for (int i = 0; i < 8; ++i)
        #pragma unroll
        for (int j = 0; j < 8; ++j) acc[i][j] = 0.f;

    float4 pa[2], pb[4];
    #pragma unroll
    for (int u = 0; u < 2; ++u) {
        int f = tid + u * 128;
        int r = f >> 2, kc = (f & 3) << 2;
        int grow = row0 + r;
        pa[u] = (grow < M) ? *(const float4*)(A + (size_t)grow * K + kc)
                           : make_float4(0.f, 0.f, 0.f, 0.f);
    }
    #pragma unroll
    for (int u = 0; u < 4; ++u) {
        int f = tid + u * 128;
        int rb = f >> 5, cb = (f & 31) << 2;
        pb[u] = *(const float4*)(B + (size_t)rb * 256 + cc + cb);
    }

    for (int kb = 0; kb < K / 16; ++kb) {
        #pragma unroll
        for (int u = 0; u < 2; ++u) {
            int f = tid + u * 128;
            int r = f >> 2, kc = (f & 3) << 2;
            As[kc + 0][r] = pa[u].x; As[kc + 1][r] = pa[u].y;
            As[kc + 2][r] = pa[u].z; As[kc + 3][r] = pa[u].w;
        }
        #pragma unroll
        for (int u = 0; u < 4; ++u) {
            int f = tid + u * 128;
            int rb = f >> 5, cb = (f & 31) << 2;
            *(float4*)&Bs[rb][cb] = pb[u];
        }
        __syncthreads();
        if (kb + 1 < K / 16) {
            int k0 = (kb + 1) * 16;
            #pragma unroll
            for (int u = 0; u < 2; ++u) {
                int f = tid + u * 128;
                int r = f >> 2, kc = (f & 3) << 2;
                int grow = row0 + r;
                pa[u] = (grow < M) ? *(const float4*)(A + (size_t)grow * K + k0 + kc)
                                   : make_float4(0.f, 0.f, 0.f, 0.f);
            }
            #pragma unroll
            for (int u = 0; u < 4; ++u) {
                int f = tid + u * 128;
                int rb = f >> 5, cb = (f & 31) << 2;
                pb[u] = *(const float4*)(B + (size_t)(k0 + rb) * 256 + cc + cb);
            }
        }
        #pragma unroll
        for (int kk = 0; kk < 16; ++kk) {
            float4 a0 = *(float4*)&As[kk][ty * 8];
            float4 a1 = *(float4*)&As[kk][ty * 8 + 4];
            float4 b0 = *(float4*)&Bs[kk][tx * 8];
            float4 b1 = *(float4*)&Bs[kk][tx * 8 + 4];
            float av[8] = {a0.x, a0.y, a0.z, a0.w, a1.x, a1.y, a1.z, a1.w};
            float bv[8] = {b0.x, b0.y, b0.z, b0.w, b1.x, b1.y, b1.z, b1.w};
            #pragma unroll
            for (int i = 0; i < 8; ++i)
                #pragma unroll
                for (int j = 0; j < 8; ++j) acc[i][j] += av[i] * bv[j];
        }
        __syncthreads();
    }

    float4 bv0 = *(const float4*)(bias + cc + tx * 8);
    float4 bv1 = *(const float4*)(bias + cc + tx * 8 + 4);
    #pragma unroll
    for (int i = 0; i < 8; ++i) {
        int grow = row0 + ty * 8 + i;
        if (grow >= M) continue;
        float4 o0 = make_float4(acc[i][0] + bv0.x, acc[i][1] + bv0.y,
                                acc[i][2] + bv0.z, acc[i][3] + bv0.w);
        float4 o1 = make_float4(acc[i][4] + bv1.x, acc[i][5] + bv1.y,
                                acc[i][6] + bv1.z, acc[i][7] + bv1.w);
        float4* cp = (float4*)(C + (size_t)grow * 256 + cc + tx * 8);
        cp[0] = o0; cp[1] = o1;
    }
}

// Policy variant: C(Mx128) = relu(A(Mx256) @ B(256x128) + bias). grid 157.
__global__ void __launch_bounds__(128, 4)
k_gemm_p(const float* __restrict__ A, const float* __restrict__ B,
         const float* __restrict__ bias, float* __restrict__ C, int M) {
    const int K = 256;
    __shared__ float As[16][68];
    __shared__ float Bs[16][128];
    int row0 = blockIdx.x * 64;
    int tid = threadIdx.x;
    int tx = tid & 15, ty = tid >> 4;

    float acc[8][8];
    #pragma unroll
    for (int i = 0; i < 8; ++i)
        #pragma unroll
        for (int j = 0; j < 8; ++j) acc[i][j] = 0.f;

    float4 pa[2], pb[4];
    #pragma unroll
    for (int u = 0; u < 2; ++u) {
        int f = tid + u * 128;
        int r = f >> 2, kc = (f & 3) << 2;
        int grow = row0 + r;
        pa[u] = (grow < M) ? *(const float4*)(A + (size_t)grow * K + kc)
                           : make_float4(0.f, 0.f, 0.f, 0.f);
    }
    #pragma unroll
    for (int u = 0; u < 4; ++u) {
        int f = tid + u * 128;
        int rb = f >> 5, cb = (f & 31) << 2;
        pb[u] = *(const float4*)(B + (size_t)rb * 128 + cb);
    }

    for (int kb = 0; kb < K / 16; ++kb) {
        #pragma unroll
        for (int u = 0; u < 2; ++u) {
            int f = tid + u * 128;
            int r = f >> 2, kc = (f & 3) << 2;
            As[kc + 0][r] = pa[u].x; As[kc + 1][r] = pa[u].y;
            As[kc + 2][r] = pa[u].z; As[kc + 3][r] = pa[u].w;
        }
        #pragma unroll
        for (int u = 0; u < 4; ++u) {
            int f = tid + u * 128;
            int rb = f >> 5, cb = (f & 31) << 2;
            *(float4*)&Bs[rb][cb] = pb[u];
        }
        __syncthreads();
        if (kb + 1 < K / 16) {
            int k0 = (kb + 1) * 16;
            #pragma unroll
            for (int u = 0; u < 2; ++u) {
                int f = tid + u * 128;
                int r = f >> 2, kc = (f & 3) << 2;
                int grow = row0 + r;
                pa[u] = (grow < M) ? *(const float4*)(A + (size_t)grow * K + k0 + kc)
                                   : make_float4(0.f, 0.f, 0.f, 0.f);
            }
            #pragma unroll
            for (int u = 0; u < 4; ++u) {
                int f = tid + u * 128;
                int rb = f >> 5, cb = (f & 31) << 2;
                pb[u] = *(const float4*)(B + (size_t)(k0 + rb) * 128 + cb);
            }
        }
        #pragma unroll
        for (int kk = 0; kk < 16; ++kk) {
            float4 a0 = *(float4*)&As[kk][ty * 8];
            float4 a1 = *(float4*)&As[kk][ty * 8 + 4];
            float4 b0 = *(float4*)&Bs[kk][tx * 8];
            float4 b1 = *(float4*)&Bs[kk][tx * 8 + 4];
            float av[8] = {a0.x, a0.y, a0.z, a0.w, a1.x, a1.y, a1.z, a1.w};
            float bv[8] = {b0.x, b0.y, b0.z, b0.w, b1.x, b1.y, b1.z, b1.w};
            #pragma unroll
            for (int i = 0; i < 8; ++i)
                #pragma unroll
                for (int j = 0; j < 8; ++j) acc[i][j] += av[i] * bv[j];
        }
        __syncthreads();
    }

    float4 bv0 = *(const float4*)(bias + tx * 8);
    float4 bv1 = *(const float4*)(bias + tx * 8 + 4);
    #pragma unroll
    for (int i = 0; i < 8; ++i) {
        int grow = row0 + ty * 8 + i;
        if (grow >= M) continue;
        float4 o0 = make_float4(fmaxf(acc[i][0] + bv0.x, 0.f), fmaxf(acc[i][1] + bv0.y, 0.f),
                                fmaxf(acc[i][2] + bv0.z, 0.f), fmaxf(acc[i][3] + bv0.w, 0.f));
        float4 o1 = make_float4(fmaxf(acc[i][4] + bv1.x, 0.f), fmaxf(acc[i][5] + bv1.y, 0.f),
                                fmaxf(acc[i][6] + bv1.z, 0.f), fmaxf(acc[i][7] + bv1.w, 0.f));
        float4* cp = (float4*)(C + (size_t)grow * 128 + tx * 8);
        cp[0] = o0; cp[1] = o1;
    }
}

// ---------------- p1 @ Wp2 + bp2 -> logits (warp per node) --------------------
__global__ void k_wp2(const float* __restrict__ Wp2, const float* __restrict__ bp2) {
    __shared__ float Ws[128 * 4];
    int tid = threadIdx.x;
    for (int i = tid; i < 128 * 4; i += blockDim.x) Ws[i] = Wp2[i];
    __syncthreads();
    int warp = (blockIdx.x * blockDim.x + tid) >> 5;
    int lane = tid & 31;
    if (warp >= NN) return;
    int n = warp;
    float o[4] = {0.f, 0.f, 0.f, 0.f};
    #pragma unroll
    for (int i = 0; i < 4; ++i) {
        int k = lane + 32 * i;
        float p = g_p1[(size_t)n * 128 + k];
        #pragma unroll
        for (int j = 0; j < 4; ++j) o[j] += p * Ws[k * 4 + j];
    }
    #pragma unroll
    for (int j = 0; j < 4; ++j) {
        #pragma unroll
        for (int off = 16; off > 0; off >>= 1)
            o[j] += __shfl_xor_sync(0xffffffffu, o[j], off);
    }
    if (lane == 0) {
        #pragma unroll
        for (int j = 0; j < 4; ++j) g_logits[n * 4 + j] = o[j] + bp2[j];
    }
}

// ---------------- global softmax over 40000 logits (single block) -------------
__global__ void k_softmax(float* __restrict__ out) {
    __shared__ float sm[1024];
    int tid = threadIdx.x;
    float m = -1e30f;
    for (int i = tid; i < NN * 4; i += 1024) m = fmaxf(m, g_logits[i]);
    sm[tid] = m;
    __syncthreads();
    for (int o = 512; o > 0; o >>= 1) {
        if (tid < o) sm[tid] = fmaxf(sm[tid], sm[tid + o]);
        __syncthreads();
    }
    float M = sm[0];
    __syncthreads();
    float s = 0.f;
    for (int i = tid; i < NN * 4; i += 1024) s += expf(g_logits[i] - M);
    sm[tid] = s;
    __syncthreads();
    for (int o = 512; o > 0; o >>= 1) {
        if (tid < o) sm[tid] += sm[tid + o];
        __syncthreads();
    }
    float inv = 1.f / sm[0];
    for (int i = tid; i < NN * 4; i += 1024) out[i] = expf(g_logits[i] - M) * inv;
}

// ---------------- launch ------------------------------------------------------
// NOTE: __device__ symbols must NOT be passed directly as kernel args from host
// code (ATS silently reads the host shadow). Use cudaGetSymbolAddress.
extern "C" void kernel_launch(void* const* d_in, const int* in_sizes, int n_in,
                              void* d_out, int out_size) {
    const float* x     = (const float*)d_in[0];
    const int*   ei    = (const int*)d_in[1];
    const float* eattr = (const float*)d_in[2];
    const float* Wl1 = (const float*)d_in[3];
    const float* bl1 = (const float*)d_in[4];
    const float* Wr1 = (const float*)d_in[5];
    const float* br1 = (const float*)d_in[6];
    const float* We1 = (const float*)d_in[7];
    const float* att1 = (const float*)d_in[8];
    const float* bias1 = (const float*)d_in[9];
    const float* g1  = (const float*)d_in[10];
    const float* be1 = (const float*)d_in[11];
    const float* Wl2 = (const float*)d_in[12];
    const float* bl2 = (const float*)d_in[13];
    const float* Wr2 = (const float*)d_in[14];
    const float* br2 = (const float*)d_in[15];
    const float* We2 = (const float*)d_in[16];
    const float* att2 = (const float*)d_in[17];
    const float* bias2 = (const float*)d_in[18];
    const float* g2  = (const float*)d_in[19];
    const float* be2 = (const float*)d_in[20];
    const float* Wp1 = (const float*)d_in[21];
    const float* bp1 = (const float*)d_in[22];
    const float* Wp2 = (const float*)d_in[23];
    const float* bp2 = (const float*)d_in[24];
    float* out = (float*)d_out;

    void* pv;
    float *xl, *xr, *h, *hn, *p1;
    cudaGetSymbolAddress(&pv, g_xl);  xl = (float*)pv;
    cudaGetSymbolAddress(&pv, g_xr);  xr = (float*)pv;
    cudaGetSymbolAddress(&pv, g_h);   h  = (float*)pv;
    cudaGetSymbolAddress(&pv, g_hn);  hn = (float*)pv;
    cudaGetSymbolAddress(&pv, g_p1);  p1 = (float*)pv;

    // preprocessing
    k_init<<<(NN + 255) / 256, 256>>>();
    k_degree<<<(EE + 255) / 256, 256>>>(ei, eattr);
    k_scan<<<1, 1024>>>();
    k_scatter<<<(EA + 255) / 256, 256>>>(ei, eattr);

    // conv1 (H=4, C=64): fused rank-4 aggregation
    k_edge_agg1<<<(NN * 32 + 255) / 256, 256>>>(x, Wl1, bl1, Wr1, br1, We1, att1, bias1, h);
    k_ln_relu<<<(NN * 32 + 255) / 256, 256>>>(h, g1, be1, hn);

    // conv2 (H=1, C=256): flat dual GEMM (157 M-tiles x 4) then gather-aggregate
    k_gemm_dual<<<157 * 4, 128>>>(hn, Wl2, Wr2, bl2, br2, xl, xr, NN);
    k_edge_agg2<<<(NN * 32 + 255) / 256, 256>>>(We2, att2, bias2, h);
    k_ln_relu<<<(NN * 32 + 255) / 256, 256>>>(h, g2, be2, hn);

    // policy head
    k_gemm_p<<<157, 128>>>(hn, Wp1, bp1, p1, NN);
    k_wp2<<<(NN * 32 + 255) / 256, 256>>>(Wp2, bp2);

    // global softmax (single block, deterministic)
    k_softmax<<<1, 1024>>>(out);
}